// round 13
// baseline (speedup 1.0000x reference)
#include <cuda_runtime.h>
#include <math.h>

#define NV 2
#define NB 16384
#define NC 100
#define ND 512
#define CHUNKS 4
#define MAIN_BLOCKS (NV * NC * CHUNKS)            // 800
#define TOTAL_BLOCKS (MAIN_BLOCKS + NV)           // 802
#define MARGIN_F 10.0f

// Scratch (no dynamic allocation allowed)
__device__ int   g_rowidx[NC * NB];               // per-class compacted row lists
__device__ int   g_ccount[NC];                    // per-class counts
__device__ float g_partials[MAIN_BLOCKS];         // per-block diff^2 partial sums
__device__ float g_inter[NV];                     // per-v inter_loss

// ---- build: one block per class, deterministic stream compaction ----
__global__ void __launch_bounds__(256) build_lists(const int* __restrict__ label)
{
    const int c    = blockIdx.x;
    const int tid  = threadIdx.x;
    const int warp = tid >> 5;
    const int lane = tid & 31;

    __shared__ int s_base;
    __shared__ int s_wtot[8];
    if (tid == 0) s_base = 0;
    __syncthreads();

    for (int base = 0; base < NB; base += 256) {
        int i = base + tid;
        bool m = (label[i] == c);
        unsigned mask = __ballot_sync(0xffffffffu, m);
        int wpos = __popc(mask & ((1u << lane) - 1u));
        if (lane == 0) s_wtot[warp] = __popc(mask);
        __syncthreads();
        int wbase = 0, total = 0;
        #pragma unroll
        for (int w = 0; w < 8; w++) {
            if (w < warp) wbase += s_wtot[w];
            total += s_wtot[w];
        }
        if (m) g_rowidx[c * NB + s_base + wbase + wpos] = i;
        __syncthreads();
        if (tid == 0) s_base += total;
        __syncthreads();
    }
    if (tid == 0) g_ccount[c] = s_base;
}

// ---- main: block = (v, class, chunk); center staged in SMEM ----
__global__ void __launch_bounds__(256) anchor_loss_main(
    const float* __restrict__ feat,
    const float* __restrict__ anchor,
    float* __restrict__ out)                      // out[0]=loss, out[1..]=sims
{
    const int tid  = threadIdx.x;
    const int warp = tid >> 5;
    const int lane = tid & 31;

    if (blockIdx.x < MAIN_BLOCKS) {
        const int v     = blockIdx.x / (NC * CHUNKS);
        const int rem   = blockIdx.x % (NC * CHUNKS);
        const int c     = rem / CHUNKS;
        const int chunk = rem % CHUNKS;

        __shared__ float4 sc[ND / 4];             // 2 KB center row
        __shared__ float  s_cn;
        __shared__ float  s_wsum[8];

        // stage center row (128 float4 by first 128 threads)
        const float4* c4 = reinterpret_cast<const float4*>(anchor)
                           + ((size_t)v * NC + c) * (ND / 4);
        if (tid < 128) sc[tid] = c4[tid];
        __syncthreads();

        // warp 0 computes ||c||^2 once
        if (warp == 0) {
            float cn = 0.f;
            #pragma unroll
            for (int k = 0; k < 4; k++) {
                float4 x = sc[lane + 32 * k];
                cn = fmaf(x.x, x.x, fmaf(x.y, x.y, fmaf(x.z, x.z, fmaf(x.w, x.w, cn))));
            }
            #pragma unroll
            for (int off = 16; off > 0; off >>= 1)
                cn += __shfl_xor_sync(0xffffffffu, cn, off);
            if (lane == 0) s_cn = cn;
        }
        __syncthreads();
        const float cn    = s_cn;
        const float cnorm = fmaxf(sqrtf(cn), 1e-8f);
        const int   n     = g_ccount[c];

        float dsum = 0.f;                         // accumulated on lane 0 only
        int j = chunk * 8 + warp;                 // 32 warp-slots stride the list
        int row = (j < n) ? g_rowidx[c * NB + j] : 0;
        for (; j < n; j += 32) {
            int nrow = (j + 32 < n) ? g_rowidx[c * NB + j + 32] : 0;  // prefetch
            const float4* f4 = reinterpret_cast<const float4*>(feat)
                               + ((size_t)v * NB + row) * (ND / 4);
            float dt = 0.f, fn = 0.f;
            #pragma unroll
            for (int k = 0; k < 4; k++) {
                float4 f = f4[lane + 32 * k];
                float4 cc = sc[lane + 32 * k];
                dt = fmaf(f.x, cc.x, fmaf(f.y, cc.y, fmaf(f.z, cc.z, fmaf(f.w, cc.w, dt))));
                fn = fmaf(f.x, f.x, fmaf(f.y, f.y, fmaf(f.z, f.z, fmaf(f.w, f.w, fn))));
            }
            #pragma unroll
            for (int off = 16; off > 0; off >>= 1) {
                dt += __shfl_xor_sync(0xffffffffu, dt, off);
                fn += __shfl_xor_sync(0xffffffffu, fn, off);
            }
            if (lane == 0) {
                out[1 + v * NB + row] = dt / (fmaxf(sqrtf(fn), 1e-8f) * cnorm);
                dsum += fn - 2.f * dt + cn;       // ||f-c||^2
            }
            row = nrow;
        }

        if (lane == 0) s_wsum[warp] = dsum;
        __syncthreads();
        if (tid == 0) {
            float t = 0.f;
            #pragma unroll
            for (int w = 0; w < 8; w++) t += s_wsum[w];
            g_partials[blockIdx.x] = t;
        }
    } else {
        // ---- anchor stats: one block per v ----
        // pair_sum = C * sum_c ||a_c||^2 - ||sum_c a_c||^2 (pd diagonal is 0)
        const int v = blockIdx.x - MAIN_BLOCKS;
        const int t = tid;                        // covers d and d+256
        const float* a = anchor + (size_t)v * NC * ND;

        float m0 = 0.f, m1 = 0.f, s = 0.f;
        #pragma unroll 4
        for (int c = 0; c < NC; c++) {
            float x0 = a[(size_t)c * ND + t];
            float x1 = a[(size_t)c * ND + t + 256];
            m0 += x0; m1 += x1;
            s = fmaf(x0, x0, fmaf(x1, x1, s));
        }
        float q = fmaf(m0, m0, m1 * m1);

        __shared__ float shs[256], shq[256];
        shs[t] = s; shq[t] = q;
        __syncthreads();
        #pragma unroll
        for (int off = 128; off > 0; off >>= 1) {
            if (t < off) { shs[t] += shs[t + off]; shq[t] += shq[t + off]; }
            __syncthreads();
        }
        if (t == 0) {
            float S  = shs[0];
            float M2 = shq[0];
            float inter = (NC * S - M2) / (float)(NC * (NC - 1));
            g_inter[v] = fmaxf(MARGIN_F - inter, 0.0f);
        }
    }
}

__global__ void __launch_bounds__(256) anchor_loss_finalize(float* __restrict__ out)
{
    const int t = threadIdx.x;                    // 256 threads; 800 partials
    float p = g_partials[t] + g_partials[t + 256] + g_partials[t + 512];  // 768
    if (t < MAIN_BLOCKS - 768) p += g_partials[t + 768];                  // +32
    __shared__ float s0[256];
    s0[t] = p;
    __syncthreads();
    #pragma unroll
    for (int off = 128; off > 0; off >>= 1) {
        if (t < off) s0[t] += s0[t + off];
        __syncthreads();
    }
    if (t == 0) {
        float center_mean = s0[0] / (2.0f * (float)NV * (float)NB);
        float inter_mean  = (g_inter[0] + g_inter[1]) / (float)NV;
        out[0] = center_mean + inter_mean;
    }
}

extern "C" void kernel_launch(void* const* d_in, const int* in_sizes, int n_in,
                              void* d_out, int out_size)
{
    const float* feat   = (const float*)d_in[0];
    const int*   label  = (const int*)d_in[1];
    const float* anchor = (const float*)d_in[2];
    float* out = (float*)d_out;

    build_lists<<<NC, 256>>>(label);
    anchor_loss_main<<<TOTAL_BLOCKS, 256>>>(feat, anchor, out);
    anchor_loss_finalize<<<1, 256>>>(out);
}

// round 14
// speedup vs baseline: 2.1829x; 2.1829x over previous
#include <cuda_runtime.h>
#include <math.h>

#define NV 2
#define NB 16384
#define NC 100
#define ND 512
#define CHUNKS 4
#define MAIN_BLOCKS (NV * NC * CHUNKS)            // 800
#define TOTAL_BLOCKS (MAIN_BLOCKS + NV)           // 802
#define MARGIN_F 10.0f

// Scratch (no dynamic allocation allowed)
__device__ int   g_rowidx[NC * NB];               // per-class compacted row lists
__device__ int   g_ccount[NC];                    // per-class counts (zero-init; reset by finalize)
__device__ float g_partials[MAIN_BLOCKS];         // per-block diff^2 partial sums
__device__ float g_inter[NV];                     // per-v inter_loss

// ---- build: one pass, scatter with atomics (~164 ops/class address) ----
__global__ void __launch_bounds__(256) build_lists(const int* __restrict__ label)
{
    const int i = blockIdx.x * 256 + threadIdx.x;    // 64 blocks * 256 = 16384
    int l = min(max(__ldg(&label[i]), 0), NC - 1);
    int slot = atomicAdd(&g_ccount[l], 1);
    g_rowidx[l * NB + slot] = i;
}

// ---- main: block = (v, class, chunk); center staged in SMEM ----
__global__ void __launch_bounds__(256) anchor_loss_main(
    const float* __restrict__ feat,
    const float* __restrict__ anchor,
    float* __restrict__ out)                      // out[0]=loss, out[1..]=sims
{
    const int tid  = threadIdx.x;
    const int warp = tid >> 5;
    const int lane = tid & 31;

    if (blockIdx.x < MAIN_BLOCKS) {
        const int v     = blockIdx.x / (NC * CHUNKS);
        const int rem   = blockIdx.x % (NC * CHUNKS);
        const int c     = rem / CHUNKS;
        const int chunk = rem % CHUNKS;

        __shared__ float4 sc[ND / 4];             // 2 KB center row
        __shared__ float  s_cn;
        __shared__ float  s_wsum[8];

        // stage center row (128 float4 by first 128 threads)
        const float4* c4 = reinterpret_cast<const float4*>(anchor)
                           + ((size_t)v * NC + c) * (ND / 4);
        if (tid < 128) sc[tid] = c4[tid];
        __syncthreads();

        // warp 0 computes ||c||^2 once
        if (warp == 0) {
            float cn = 0.f;
            #pragma unroll
            for (int k = 0; k < 4; k++) {
                float4 x = sc[lane + 32 * k];
                cn = fmaf(x.x, x.x, fmaf(x.y, x.y, fmaf(x.z, x.z, fmaf(x.w, x.w, cn))));
            }
            #pragma unroll
            for (int off = 16; off > 0; off >>= 1)
                cn += __shfl_xor_sync(0xffffffffu, cn, off);
            if (lane == 0) s_cn = cn;
        }
        __syncthreads();
        const float cn    = s_cn;
        const float cnorm = fmaxf(sqrtf(cn), 1e-8f);
        const int   n     = g_ccount[c];

        float dsum = 0.f;                         // accumulated on lane 0 only
        int j = chunk * 8 + warp;                 // 32 warp-slots stride the list
        int row = (j < n) ? g_rowidx[c * NB + j] : 0;
        for (; j < n; j += 32) {
            int nrow = (j + 32 < n) ? g_rowidx[c * NB + j + 32] : 0;  // prefetch
            const float4* f4 = reinterpret_cast<const float4*>(feat)
                               + ((size_t)v * NB + row) * (ND / 4);
            float dt = 0.f, fn = 0.f;
            #pragma unroll
            for (int k = 0; k < 4; k++) {
                float4 f = f4[lane + 32 * k];
                float4 cc = sc[lane + 32 * k];
                dt = fmaf(f.x, cc.x, fmaf(f.y, cc.y, fmaf(f.z, cc.z, fmaf(f.w, cc.w, dt))));
                fn = fmaf(f.x, f.x, fmaf(f.y, f.y, fmaf(f.z, f.z, fmaf(f.w, f.w, fn))));
            }
            #pragma unroll
            for (int off = 16; off > 0; off >>= 1) {
                dt += __shfl_xor_sync(0xffffffffu, dt, off);
                fn += __shfl_xor_sync(0xffffffffu, fn, off);
            }
            if (lane == 0) {
                out[1 + v * NB + row] = dt / (fmaxf(sqrtf(fn), 1e-8f) * cnorm);
                dsum += fn - 2.f * dt + cn;       // ||f-c||^2
            }
            row = nrow;
        }

        if (lane == 0) s_wsum[warp] = dsum;
        __syncthreads();
        if (tid == 0) {
            float t = 0.f;
            #pragma unroll
            for (int w = 0; w < 8; w++) t += s_wsum[w];
            g_partials[blockIdx.x] = t;
        }
    } else {
        // ---- anchor stats: one block per v ----
        // pair_sum = C * sum_c ||a_c||^2 - ||sum_c a_c||^2 (pd diagonal is 0)
        const int v = blockIdx.x - MAIN_BLOCKS;
        const int t = tid;                        // covers d and d+256
        const float* a = anchor + (size_t)v * NC * ND;

        float m0 = 0.f, m1 = 0.f, s = 0.f;
        #pragma unroll 4
        for (int c = 0; c < NC; c++) {
            float x0 = a[(size_t)c * ND + t];
            float x1 = a[(size_t)c * ND + t + 256];
            m0 += x0; m1 += x1;
            s = fmaf(x0, x0, fmaf(x1, x1, s));
        }
        float q = fmaf(m0, m0, m1 * m1);

        __shared__ float shs[256], shq[256];
        shs[t] = s; shq[t] = q;
        __syncthreads();
        #pragma unroll
        for (int off = 128; off > 0; off >>= 1) {
            if (t < off) { shs[t] += shs[t + off]; shq[t] += shq[t + off]; }
            __syncthreads();
        }
        if (t == 0) {
            float S  = shs[0];
            float M2 = shq[0];
            float inter = (NC * S - M2) / (float)(NC * (NC - 1));
            g_inter[v] = fmaxf(MARGIN_F - inter, 0.0f);
        }
    }
}

__global__ void __launch_bounds__(256) anchor_loss_finalize(float* __restrict__ out)
{
    const int t = threadIdx.x;                    // 256 threads; 800 partials
    float p = g_partials[t] + g_partials[t + 256] + g_partials[t + 512];  // 768
    if (t < MAIN_BLOCKS - 768) p += g_partials[t + 768];                  // +32
    __shared__ float s0[256];
    s0[t] = p;
    __syncthreads();
    #pragma unroll
    for (int off = 128; off > 0; off >>= 1) {
        if (t < off) s0[t] += s0[t + off];
        __syncthreads();
    }
    if (t == 0) {
        float center_mean = s0[0] / (2.0f * (float)NV * (float)NB);
        float inter_mean  = (g_inter[0] + g_inter[1]) / (float)NV;
        out[0] = center_mean + inter_mean;
    }
    // reset class counters for the next graph replay (build re-fills them)
    if (t < NC) g_ccount[t] = 0;
}

extern "C" void kernel_launch(void* const* d_in, const int* in_sizes, int n_in,
                              void* d_out, int out_size)
{
    const float* feat   = (const float*)d_in[0];
    const int*   label  = (const int*)d_in[1];
    const float* anchor = (const float*)d_in[2];
    float* out = (float*)d_out;

    build_lists<<<64, 256>>>(label);
    anchor_loss_main<<<TOTAL_BLOCKS, 256>>>(feat, anchor, out);
    anchor_loss_finalize<<<1, 256>>>(out);
}

// round 15
// speedup vs baseline: 2.1863x; 1.0015x over previous
#include <cuda_runtime.h>
#include <math.h>

#define NV 2
#define NB 16384
#define NC 100
#define ND 512
#define CHUNKS 2
#define MAIN_BLOCKS (NV * NC * CHUNKS)            // 400
#define TOTAL_BLOCKS (MAIN_BLOCKS + NV)           // 402
#define MARGIN_F 10.0f

// Scratch (no dynamic allocation allowed)
__device__ int   g_rowidx[NC * NB];               // per-class compacted row lists
__device__ int   g_ccount[NC];                    // per-class counts (zero-init; reset by finalize)
__device__ float g_partials[MAIN_BLOCKS];         // per-block diff^2 partial sums
__device__ float g_inter[NV];                     // per-v inter_loss

// ---- build: two-level (SMEM histogram -> one global reserve per block/class) ----
__global__ void __launch_bounds__(1024) build_lists(const int* __restrict__ label)
{
    __shared__ int cnt[NC];
    __shared__ int base[NC];
    const int tid = threadIdx.x;
    if (tid < NC) cnt[tid] = 0;
    __syncthreads();

    const int i = blockIdx.x * 1024 + tid;        // 16 blocks * 1024 = 16384
    int l = min(max(__ldg(&label[i]), 0), NC - 1);
    int slot = atomicAdd(&cnt[l], 1);             // SMEM: spread-address, fast
    __syncthreads();

    if (tid < NC) base[tid] = atomicAdd(&g_ccount[tid], cnt[tid]);  // 16-deep only
    __syncthreads();

    g_rowidx[l * NB + base[l] + slot] = i;
}

// ---- main: block = (v, class, chunk); center staged in SMEM; 512 threads ----
__global__ void __launch_bounds__(512) anchor_loss_main(
    const float* __restrict__ feat,
    const float* __restrict__ anchor,
    float* __restrict__ out)                      // out[0]=loss, out[1..]=sims
{
    const int tid  = threadIdx.x;
    const int warp = tid >> 5;
    const int lane = tid & 31;

    if (blockIdx.x < MAIN_BLOCKS) {
        const int v     = blockIdx.x / (NC * CHUNKS);
        const int rem   = blockIdx.x % (NC * CHUNKS);
        const int c     = rem / CHUNKS;
        const int chunk = rem % CHUNKS;

        __shared__ float4 sc[ND / 4];             // 2 KB center row
        __shared__ float  s_cn;
        __shared__ float  s_wsum[16];

        // stage center row (128 float4 by first 128 threads)
        const float4* c4 = reinterpret_cast<const float4*>(anchor)
                           + ((size_t)v * NC + c) * (ND / 4);
        if (tid < 128) sc[tid] = c4[tid];
        __syncthreads();

        // warp 0 computes ||c||^2 once
        if (warp == 0) {
            float cn = 0.f;
            #pragma unroll
            for (int k = 0; k < 4; k++) {
                float4 x = sc[lane + 32 * k];
                cn = fmaf(x.x, x.x, fmaf(x.y, x.y, fmaf(x.z, x.z, fmaf(x.w, x.w, cn))));
            }
            #pragma unroll
            for (int off = 16; off > 0; off >>= 1)
                cn += __shfl_xor_sync(0xffffffffu, cn, off);
            if (lane == 0) s_cn = cn;
        }
        __syncthreads();
        const float cn    = s_cn;
        const float cnorm = fmaxf(sqrtf(cn), 1e-8f);
        const int   n     = g_ccount[c];

        float dsum = 0.f;                         // accumulated on lane 0 only
        int j = chunk * 16 + warp;                // 32 warp-slots stride the list
        int row = (j < n) ? g_rowidx[c * NB + j] : 0;
        for (; j < n; j += 32) {
            int nrow = (j + 32 < n) ? g_rowidx[c * NB + j + 32] : 0;  // prefetch
            const float4* f4 = reinterpret_cast<const float4*>(feat)
                               + ((size_t)v * NB + row) * (ND / 4);
            float dt = 0.f, fn = 0.f;
            #pragma unroll
            for (int k = 0; k < 4; k++) {
                float4 f = f4[lane + 32 * k];
                float4 cc = sc[lane + 32 * k];
                dt = fmaf(f.x, cc.x, fmaf(f.y, cc.y, fmaf(f.z, cc.z, fmaf(f.w, cc.w, dt))));
                fn = fmaf(f.x, f.x, fmaf(f.y, f.y, fmaf(f.z, f.z, fmaf(f.w, f.w, fn))));
            }
            #pragma unroll
            for (int off = 16; off > 0; off >>= 1) {
                dt += __shfl_xor_sync(0xffffffffu, dt, off);
                fn += __shfl_xor_sync(0xffffffffu, fn, off);
            }
            if (lane == 0) {
                out[1 + v * NB + row] = dt / (fmaxf(sqrtf(fn), 1e-8f) * cnorm);
                dsum += fn - 2.f * dt + cn;       // ||f-c||^2
            }
            row = nrow;
        }

        if (lane == 0) s_wsum[warp] = dsum;
        __syncthreads();
        if (tid == 0) {
            float t = 0.f;
            #pragma unroll
            for (int w = 0; w < 16; w++) t += s_wsum[w];
            g_partials[blockIdx.x] = t;
        }
    } else {
        // ---- anchor stats: one block per v (512 threads = one per d) ----
        // pair_sum = C * sum_c ||a_c||^2 - ||sum_c a_c||^2 (pd diagonal is 0)
        const int v = blockIdx.x - MAIN_BLOCKS;
        const int t = tid;                        // 0..511 = d index
        const float* a = anchor + (size_t)v * NC * ND;

        float m = 0.f, s = 0.f;
        #pragma unroll 4
        for (int c = 0; c < NC; c++) {
            float x = a[(size_t)c * ND + t];
            m += x;
            s = fmaf(x, x, s);
        }
        float q = m * m;

        __shared__ float shs[512], shq[512];
        shs[t] = s; shq[t] = q;
        __syncthreads();
        #pragma unroll
        for (int off = 256; off > 0; off >>= 1) {
            if (t < off) { shs[t] += shs[t + off]; shq[t] += shq[t + off]; }
            __syncthreads();
        }
        if (t == 0) {
            float S  = shs[0];
            float M2 = shq[0];
            float inter = (NC * S - M2) / (float)(NC * (NC - 1));
            g_inter[v] = fmaxf(MARGIN_F - inter, 0.0f);
        }
    }
}

__global__ void __launch_bounds__(256) anchor_loss_finalize(float* __restrict__ out)
{
    const int t = threadIdx.x;                    // 256 threads; 400 partials
    float p = g_partials[t];
    if (t + 256 < MAIN_BLOCKS) p += g_partials[t + 256];
    __shared__ float s0[256];
    s0[t] = p;
    __syncthreads();
    #pragma unroll
    for (int off = 128; off > 0; off >>= 1) {
        if (t < off) s0[t] += s0[t + off];
        __syncthreads();
    }
    if (t == 0) {
        float center_mean = s0[0] / (2.0f * (float)NV * (float)NB);
        float inter_mean  = (g_inter[0] + g_inter[1]) / (float)NV;
        out[0] = center_mean + inter_mean;
    }
    // reset class counters for the next graph replay (build re-fills them)
    if (t < NC) g_ccount[t] = 0;
}

extern "C" void kernel_launch(void* const* d_in, const int* in_sizes, int n_in,
                              void* d_out, int out_size)
{
    const float* feat   = (const float*)d_in[0];
    const int*   label  = (const int*)d_in[1];
    const float* anchor = (const float*)d_in[2];
    float* out = (float*)d_out;

    build_lists<<<16, 1024>>>(label);
    anchor_loss_main<<<TOTAL_BLOCKS, 512>>>(feat, anchor, out);
    anchor_loss_finalize<<<1, 256>>>(out);
}